// round 15
// baseline (speedup 1.0000x reference)
#include <cuda_runtime.h>
#include <cuda_bf16.h>

// Chamfer loss (nearest-target-vertex): B=4, N=16384, M=4096, D=3.
// d2[b,n] = p2 + 2 * min_m (0.5*|v|^2 - p.v);  loss[b] = sum_n d2[b,n] / N
//
// EXACT pruned algorithm via 1-D counting sort on x:
//   K1: histogram targets+points into 256 x-bins per batch (+ zero out[]).
//   K2: single-block scan -> bin offsets + scatter cursors; self-zeroes hist
//       (device globals start zeroed; every run re-zeroes -> replay-safe).
//   K3: counting-sort scatter. targets -> (x,y,z,0.5|v|^2), points -> (x,y,z,|p|^2).
//   K4: warp = 32 consecutive sorted points. Two-sided bin expansion from the
//       warp's bin span; per-lane exact stop bound (unexamined targets have
//       |dx| >= bin-edge margin; clamped edge bins give valid bounds; side
//       exhausted -> +inf). Exact min, ~10x fewer pair evaluations.

#define B_ 4
#define N_ 16384
#define M_ 4096
#define NB 256
#define X0f (-5.0f)
#define Hf 0.0390625f              /* 10/256, exact in binary */
#define INVHf 25.6f

#define HIST_THREADS 256
#define HIST_BLOCKS ((B_ * (M_ + N_)) / HIST_THREADS)   // 320

#define NN_THREADS 256
#define NN_BLOCKS (B_ * N_ / NN_THREADS)                // 256

__device__ float4 g_tgt_sorted[B_][M_];
__device__ float4 g_pt_sorted[B_][N_];
__device__ int    g_hist[2][B_][NB];      // [0]=targets, [1]=points
__device__ int    g_off[B_][NB + 1];      // target bin offsets
__device__ int    g_cur[2][B_][NB];       // scatter cursors

__device__ __forceinline__ int xbin(float x) {
    int j = (int)floorf((x - X0f) * INVHf);
    return min(max(j, 0), NB - 1);
}

// ---- K1: histogram (and zero out) ----
__global__ __launch_bounds__(HIST_THREADS)
void k1_hist(const float* __restrict__ src,
             const float* __restrict__ tgt,
             float* __restrict__ out) {
    if (blockIdx.x == 0 && threadIdx.x < B_) out[threadIdx.x] = 0.0f;
    int idx = blockIdx.x * HIST_THREADS + threadIdx.x;
    if (idx < B_ * M_) {
        int b = idx / M_;
        float x = tgt[(size_t)idx * 3];
        atomicAdd(&g_hist[0][b][xbin(x)], 1);
    } else {
        int r = idx - B_ * M_;
        int b = r / N_;
        float x = src[(size_t)r * 3];
        atomicAdd(&g_hist[1][b][xbin(x)], 1);
    }
}

// ---- K2: scan each (kind,batch) segment of 256 bins; init cursors; zero hist ----
__global__ __launch_bounds__(256)
void k2_scan() {
    int tid  = threadIdx.x;
    int lane = tid & 31, w = tid >> 5;
    __shared__ int wsum[8];
    for (int seg = 0; seg < 8; seg++) {
        int kind = seg >> 2, b = seg & 3;
        int c = g_hist[kind][b][tid];
        int v = c;
#pragma unroll
        for (int off = 1; off < 32; off <<= 1) {
            int t = __shfl_up_sync(0xffffffffu, v, off);
            if (lane >= off) v += t;
        }
        if (lane == 31) wsum[w] = v;
        __syncthreads();
        int base = 0;
#pragma unroll
        for (int k = 0; k < 8; k++) base += (k < w) ? wsum[k] : 0;
        int incl = v + base;
        int excl = incl - c;
        if (kind == 0) {
            g_off[b][tid] = excl;
            if (tid == NB - 1) g_off[b][NB] = incl;
        }
        g_cur[kind][b][tid] = excl;
        g_hist[kind][b][tid] = 0;          // self-reset for next replay
        __syncthreads();
    }
}

// ---- K3: counting-sort scatter ----
__global__ __launch_bounds__(HIST_THREADS)
void k3_scatter(const float* __restrict__ src,
                const float* __restrict__ tgt) {
    int idx = blockIdx.x * HIST_THREADS + threadIdx.x;
    if (idx < B_ * M_) {
        int b = idx / M_;
        float x = tgt[(size_t)idx * 3 + 0];
        float y = tgt[(size_t)idx * 3 + 1];
        float z = tgt[(size_t)idx * 3 + 2];
        int pos = atomicAdd(&g_cur[0][b][xbin(x)], 1);
        g_tgt_sorted[b][pos] = make_float4(x, y, z, 0.5f * (x*x + y*y + z*z));
    } else {
        int r = idx - B_ * M_;
        int b = r / N_;
        float x = src[(size_t)r * 3 + 0];
        float y = src[(size_t)r * 3 + 1];
        float z = src[(size_t)r * 3 + 2];
        int pos = atomicAdd(&g_cur[1][b][xbin(x)], 1);
        g_pt_sorted[b][pos] = make_float4(x, y, z, x*x + y*y + z*z);
    }
}

// ---- K4: warp-synchronous pruned NN + reduction ----
__global__ __launch_bounds__(NN_THREADS)
void k4_nn(float* __restrict__ out) {
    const unsigned FULL = 0xffffffffu;
    int gidx = blockIdx.x * NN_THREADS + threadIdx.x;
    int b = gidx >> 14;                 // 16384 points per batch
    int i = gidx & (N_ - 1);

    float4 p = g_pt_sorted[b][i];
    float nx = -p.x, ny = -p.y, nz = -p.z, p2 = p.w;

    // Warp's bin span: lanes cover consecutive sorted points, so lane 0 is in
    // the lowest bin of the warp and lane 31 in the highest.
    float x0  = __shfl_sync(FULL, p.x, 0);
    float x31 = __shfl_sync(FULL, p.x, 31);
    int jlo = xbin(x0);
    int jhi = xbin(x31);

    const int*    off = g_off[b];
    const float4* tv  = g_tgt_sorted[b];

    float best = 1e30f;
    // Initial window: all bins spanned by the warp's own points.
    for (int j = jlo; j <= jhi; j++) {
        int e = off[j + 1];
        for (int t = off[j]; t < e; t++) {
            float4 v = tv[t];          // broadcast LDG.128
            float sc = fmaf(v.z, nz, fmaf(v.y, ny, fmaf(v.x, nx, v.w)));
            best = fminf(best, sc);
        }
    }

    int nextR = jhi + 1, nextL = jlo - 1;
    while (true) {
        float bd2 = fmaxf(fmaf(2.0f, best, p2), 0.0f);   // current best d^2
        // Exact per-lane lower bounds on any unexamined target's distance.
        float dR = (nextR <= NB - 1) ? fmaxf(X0f + nextR * Hf - p.x, 0.0f) : 1e30f;
        float dL = (nextL >= 0)      ? fmaxf(p.x - (X0f + (nextL + 1) * Hf), 0.0f) : 1e30f;
        bool done = (bd2 <= dR * dR) && (bd2 <= dL * dL);
        if (__all_sync(FULL, done)) break;
        // Warp-uniform side choice (heuristic only; correctness is per-lane).
        float mR = (nextR <= NB - 1) ? (X0f + nextR * Hf - x31) : 1e30f;
        float mL = (nextL >= 0)      ? (x0 - (X0f + (nextL + 1) * Hf)) : 1e30f;
        int j;
        if (mR <= mL) { j = nextR; nextR++; }
        else          { j = nextL; nextL--; }
        int e = off[j + 1];
        for (int t = off[j]; t < e; t++) {
            float4 v = tv[t];
            float sc = fmaf(v.z, nz, fmaf(v.y, ny, fmaf(v.x, nx, v.w)));
            best = fminf(best, sc);
        }
    }

    float local = fmaxf(fmaf(2.0f, best, p2), 0.0f);     // clamped d^2

#pragma unroll
    for (int offv = 16; offv > 0; offv >>= 1)
        local += __shfl_down_sync(FULL, local, offv);

    __shared__ float warp_sums[NN_THREADS / 32];
    if ((threadIdx.x & 31) == 0) warp_sums[threadIdx.x >> 5] = local;
    __syncthreads();

    if (threadIdx.x == 0) {
        float ssum = 0.0f;
#pragma unroll
        for (int k = 0; k < NN_THREADS / 32; k++)
            ssum += warp_sums[k];
        atomicAdd(&out[b], ssum * (1.0f / N_));   // block's points: one batch
    }
}

extern "C" void kernel_launch(void* const* d_in, const int* in_sizes, int n_in,
                              void* d_out, int out_size) {
    const float* src = (const float*)d_in[0];
    const float* tgt = (const float*)d_in[1];
    if (n_in >= 2 && in_sizes[0] == B_ * M_ * 3 && in_sizes[1] == B_ * N_ * 3) {
        const float* t = src; src = tgt; tgt = t;
    }
    float* out = (float*)d_out;

    k1_hist<<<HIST_BLOCKS, HIST_THREADS>>>(src, tgt, out);
    k2_scan<<<1, 256>>>();
    k3_scatter<<<HIST_BLOCKS, HIST_THREADS>>>(src, tgt);
    k4_nn<<<NN_BLOCKS, NN_THREADS>>>(out);
}

// round 16
// speedup vs baseline: 1.6109x; 1.6109x over previous
#include <cuda_runtime.h>
#include <cuda_bf16.h>

// Chamfer loss (nearest-target-vertex): B=4, N=16384, M=4096, D=3.
// d2[b,n] = p2 + 2 * min_m (0.5*|v|^2 - p.v);  loss[b] = sum_n d2[b,n] / N
//
// EXACT pruned algorithm, dense-style inner loop:
//   K1: histogram targets+points into 256 x-bins per batch (+ zero out[]).
//   K2: single-block scan -> offsets/cursors; self-zeroes hist (replay-safe).
//   K3: counting-sort scatter into float4 arrays (w = 0.5|v|^2 / |p|^2).
//   K4: block = 256 consecutive sorted points. Candidate targets form a
//       CONTIGUOUS sorted range; copy window to smem, dense unrolled scan,
//       per-point exact bin-edge stop bound, __syncthreads_and, expand by
//       4 bins/side as needed. smem holds up to all M targets (64 KB) ->
//       exact with guaranteed termination.

#define B_ 4
#define N_ 16384
#define M_ 4096
#define NB 256
#define X0f (-5.0f)
#define Hf 0.0390625f              /* 10/256, exact in binary */
#define INVHf 25.6f
#define R0f 0.15625f               /* initial margin: 4 bins */
#define EXPB 4                     /* expansion step: bins per side */

#define HIST_THREADS 256
#define HIST_BLOCKS ((B_ * (M_ + N_)) / HIST_THREADS)   // 320

#define NN_THREADS 256
#define NN_PTS 256
#define BLKS_PER_B (N_ / NN_PTS)                        // 64
#define NN_BLOCKS (B_ * BLKS_PER_B)                     // 256
#define NN_SMEM (M_ * 16)                               // 64 KB cap

__device__ float4 g_tgt_sorted[B_][M_];
__device__ float4 g_pt_sorted[B_][N_];
__device__ int    g_hist[2][B_][NB];      // [0]=targets, [1]=points
__device__ int    g_off[B_][NB + 1];      // target bin offsets
__device__ int    g_cur[2][B_][NB];       // scatter cursors

__device__ __forceinline__ int xbin(float x) {
    int j = (int)floorf((x - X0f) * INVHf);
    return min(max(j, 0), NB - 1);
}

// ---- K1: histogram (and zero out) ----
__global__ __launch_bounds__(HIST_THREADS)
void k1_hist(const float* __restrict__ src,
             const float* __restrict__ tgt,
             float* __restrict__ out) {
    if (blockIdx.x == 0 && threadIdx.x < B_) out[threadIdx.x] = 0.0f;
    int idx = blockIdx.x * HIST_THREADS + threadIdx.x;
    if (idx < B_ * M_) {
        int b = idx / M_;
        atomicAdd(&g_hist[0][b][xbin(tgt[(size_t)idx * 3])], 1);
    } else {
        int r = idx - B_ * M_;
        int b = r / N_;
        atomicAdd(&g_hist[1][b][xbin(src[(size_t)r * 3])], 1);
    }
}

// ---- K2: scan 8 (kind,batch) segments; init cursors; zero hist ----
__global__ __launch_bounds__(256)
void k2_scan() {
    int tid  = threadIdx.x;
    int lane = tid & 31, w = tid >> 5;
    __shared__ int wsum[8];
    for (int seg = 0; seg < 8; seg++) {
        int kind = seg >> 2, b = seg & 3;
        int c = g_hist[kind][b][tid];
        int v = c;
#pragma unroll
        for (int off = 1; off < 32; off <<= 1) {
            int t = __shfl_up_sync(0xffffffffu, v, off);
            if (lane >= off) v += t;
        }
        if (lane == 31) wsum[w] = v;
        __syncthreads();
        int base = 0;
#pragma unroll
        for (int k = 0; k < 8; k++) base += (k < w) ? wsum[k] : 0;
        int incl = v + base;
        int excl = incl - c;
        if (kind == 0) {
            g_off[b][tid] = excl;
            if (tid == NB - 1) g_off[b][NB] = incl;
        }
        g_cur[kind][b][tid] = excl;
        g_hist[kind][b][tid] = 0;          // self-reset for next replay
        __syncthreads();
    }
}

// ---- K3: counting-sort scatter ----
__global__ __launch_bounds__(HIST_THREADS)
void k3_scatter(const float* __restrict__ src,
                const float* __restrict__ tgt) {
    int idx = blockIdx.x * HIST_THREADS + threadIdx.x;
    if (idx < B_ * M_) {
        int b = idx / M_;
        float x = tgt[(size_t)idx * 3 + 0];
        float y = tgt[(size_t)idx * 3 + 1];
        float z = tgt[(size_t)idx * 3 + 2];
        int pos = atomicAdd(&g_cur[0][b][xbin(x)], 1);
        g_tgt_sorted[b][pos] = make_float4(x, y, z, 0.5f * (x*x + y*y + z*z));
    } else {
        int r = idx - B_ * M_;
        int b = r / N_;
        float x = src[(size_t)r * 3 + 0];
        float y = src[(size_t)r * 3 + 1];
        float z = src[(size_t)r * 3 + 2];
        int pos = atomicAdd(&g_cur[1][b][xbin(x)], 1);
        g_pt_sorted[b][pos] = make_float4(x, y, z, x*x + y*y + z*z);
    }
}

// ---- K4: windowed dense NN with exact expansion ----
__global__ __launch_bounds__(NN_THREADS)
void k4_nn(float* __restrict__ out) {
    extern __shared__ float4 st[];     // target window (up to M_)
    __shared__ float wmin[NN_THREADS / 32], wmax[NN_THREADS / 32];

    const unsigned FULL = 0xffffffffu;
    const int tid  = threadIdx.x;
    const int lane = tid & 31, wid = tid >> 5;
    const int b   = blockIdx.x / BLKS_PER_B;
    const int i   = (blockIdx.x % BLKS_PER_B) * NN_PTS + tid;

    float4 p = g_pt_sorted[b][i];
    const float nx = -p.x, ny = -p.y, nz = -p.z, p2 = p.w;

    // Block x-span (all threads end with identical values -> uniform control).
    float xm = p.x, xM = p.x;
#pragma unroll
    for (int off = 16; off > 0; off >>= 1) {
        xm = fminf(xm, __shfl_xor_sync(FULL, xm, off));
        xM = fmaxf(xM, __shfl_xor_sync(FULL, xM, off));
    }
    if (lane == 0) { wmin[wid] = xm; wmax[wid] = xM; }
    __syncthreads();
    float bxmin = wmin[0], bxmax = wmax[0];
#pragma unroll
    for (int k = 1; k < NN_THREADS / 32; k++) {
        bxmin = fminf(bxmin, wmin[k]);
        bxmax = fmaxf(bxmax, wmax[k]);
    }

    const int*    off = g_off[b];
    const float4* tv  = g_tgt_sorted[b];

    // Initial window (bin indices + contiguous target range), uniform.
    int jlo = xbin(bxmin - R0f);
    int jhi = xbin(bxmax + R0f);
    int A   = off[jlo];            // uniform-address loads: broadcast
    int Bv  = off[jhi + 1];
    int cnt = Bv - A;

    for (int k = tid; k < cnt; k += NN_THREADS)
        st[k] = tv[A + k];
    __syncthreads();

    float best = 1e30f;
    // Dense scan helper pattern (unroll 4, two partial min chains).
    {
        float b0 = 1e30f, b1 = 1e30f;
#pragma unroll 4
        for (int t = 0; t < cnt; t++) {
            float4 v = st[t];
            float sc = fmaf(v.z, nz, fmaf(v.y, ny, fmaf(v.x, nx, v.w)));
            if (t & 1) b1 = fminf(b1, sc); else b0 = fminf(b0, sc);
        }
        best = fminf(b0, b1);
    }

    // Expansion loop: exact bin-edge bounds; append-only contiguous chunks.
    while (true) {
        float dL = (jlo > 0)      ? fmaxf(p.x - (X0f + jlo * Hf), 0.0f)       : 1e15f;
        float dR = (jhi < NB - 1) ? fmaxf((X0f + (jhi + 1) * Hf) - p.x, 0.0f) : 1e15f;
        float bd2 = fmaxf(fmaf(2.0f, best, p2), 0.0f);
        bool done = (bd2 <= dL * dL) && (bd2 <= dR * dR);
        if (__syncthreads_and(done)) break;

        int njlo = max(jlo - EXPB, 0);
        int njhi = min(jhi + EXPB, NB - 1);
        int nA   = off[njlo];
        int nB   = off[njhi + 1];
        int nL   = A - nA;            // new left targets
        int nR   = nB - Bv;           // new right targets

        for (int k = tid; k < nL; k += NN_THREADS)
            st[cnt + k] = tv[nA + k];
        for (int k = tid; k < nR; k += NN_THREADS)
            st[cnt + nL + k] = tv[Bv + k];
        __syncthreads();

        int ncnt = cnt + nL + nR;
        float b0 = 1e30f, b1 = 1e30f;
#pragma unroll 4
        for (int t = cnt; t < ncnt; t++) {
            float4 v = st[t];
            float sc = fmaf(v.z, nz, fmaf(v.y, ny, fmaf(v.x, nx, v.w)));
            if (t & 1) b1 = fminf(b1, sc); else b0 = fminf(b0, sc);
        }
        best = fminf(best, fminf(b0, b1));

        cnt = ncnt; A = nA; Bv = nB; jlo = njlo; jhi = njhi;
    }

    // Clamped d^2, block reduce, one atomic per block (single batch).
    float local = fmaxf(fmaf(2.0f, best, p2), 0.0f);
#pragma unroll
    for (int off2 = 16; off2 > 0; off2 >>= 1)
        local += __shfl_down_sync(FULL, local, off2);

    __shared__ float warp_sums[NN_THREADS / 32];
    if (lane == 0) warp_sums[wid] = local;
    __syncthreads();
    if (tid == 0) {
        float ssum = 0.0f;
#pragma unroll
        for (int k = 0; k < NN_THREADS / 32; k++)
            ssum += warp_sums[k];
        atomicAdd(&out[b], ssum * (1.0f / N_));
    }
}

extern "C" void kernel_launch(void* const* d_in, const int* in_sizes, int n_in,
                              void* d_out, int out_size) {
    const float* src = (const float*)d_in[0];
    const float* tgt = (const float*)d_in[1];
    if (n_in >= 2 && in_sizes[0] == B_ * M_ * 3 && in_sizes[1] == B_ * N_ * 3) {
        const float* t = src; src = tgt; tgt = t;
    }
    float* out = (float*)d_out;

    cudaFuncSetAttribute(k4_nn,
                         cudaFuncAttributeMaxDynamicSharedMemorySize, NN_SMEM);

    k1_hist<<<HIST_BLOCKS, HIST_THREADS>>>(src, tgt, out);
    k2_scan<<<1, 256>>>();
    k3_scatter<<<HIST_BLOCKS, HIST_THREADS>>>(src, tgt);
    k4_nn<<<NN_BLOCKS, NN_THREADS, NN_SMEM>>>(out);
}